// round 16
// baseline (speedup 1.0000x reference)
#include <cuda_runtime.h>

// SelMul: pair (i,j), i<=j, row-major triangular:
//   offset(i,j) = i*N - T(i+1) + j,  T(k) = k(k-1)/2,  value x[b,i]*x[b,j].
// x: (256,1024) fp32 -> out: (256,524800) fp32 (~537 MB). Store-bound.
//
// R15 = R12's PROVEN 16-row tile (passed, rel_err 0.0; 5 LDG.128 + 1 scalar
// load per 16 aligned STG.128 -> ~35% fewer L1 read wavefronts than the 8-row
// octet) composed with R14's geometry fixes that R12 lacked:
//  - BB=1 -> 8192 CTAs (R12 had 2048: 5.5-wave tail),
//  - warp-uniform __any_sync skip: a warp loads+stores only its own tile
//    (R12 issued all 32 predicated-off stores),
//  - __launch_bounds__(256,6) + lazy xq (R12 sat at regs=64 / 4 CTAs/SM).
// Indexing identical to R12: tile rows i0..i0+15, i0 % 16 == 0;
//   D(r) = r + ((T(r+1)&3 - r) & 3) = {0,1,3,6,6,7,9,8,8,9,11,14,14,15,17,16},
//   max D+3 = 20 -> w[0..19] from 5 LDG.128 plus scalar w20 (pick6 statically
//   bounds-checked). Heads/tails scalar via the same congruence.

static constexpr int N       = 1024;
static constexpr int B       = 256;
static constexpr int TRI     = N * (N + 1) / 2;   // 524800
static constexpr int THREADS = 256;
static constexpr int M4LAST  = N / 4 - 1;         // 255

__host__ __device__ constexpr int triang(int k) { return k * (k - 1) / 2; }
__host__ __device__ constexpr int Dof(int r) {
    return r + ((((triang(r + 1) & 3) - r) + 16) & 3);
}

// Select float K (0..15) from four float4s.
template <int K>
__device__ __forceinline__ float pick(const float4& a, const float4& b,
                                      const float4& c, const float4& d) {
    static_assert(K >= 0 && K <= 15);
    if constexpr (K == 0)  return a.x;
    else if constexpr (K == 1)  return a.y;
    else if constexpr (K == 2)  return a.z;
    else if constexpr (K == 3)  return a.w;
    else if constexpr (K == 4)  return b.x;
    else if constexpr (K == 5)  return b.y;
    else if constexpr (K == 6)  return b.z;
    else if constexpr (K == 7)  return b.w;
    else if constexpr (K == 8)  return c.x;
    else if constexpr (K == 9)  return c.y;
    else if constexpr (K == 10) return c.z;
    else if constexpr (K == 11) return c.w;
    else if constexpr (K == 12) return d.x;
    else if constexpr (K == 13) return d.y;
    else if constexpr (K == 14) return d.z;
    else return d.w;
}

// Select float K (0..20) from five float4s + one scalar (w[20]).
template <int K>
__device__ __forceinline__ float pick6(const float4& a, const float4& b,
                                       const float4& c, const float4& d,
                                       const float4& e, float w20) {
    static_assert(K >= 0 && K <= 20);
    if constexpr (K < 16)       return pick<K>(a, b, c, d);
    else if constexpr (K == 16) return e.x;
    else if constexpr (K == 17) return e.y;
    else if constexpr (K == 18) return e.z;
    else if constexpr (K == 19) return e.w;
    else                        return w20;
}

template <int R>
__device__ __forceinline__ void tile_row(bool lane_ok,
                                         const float4& w0, const float4& w1,
                                         const float4& w2, const float4& w3,
                                         const float4& w4, float w20,
                                         const float4& xq0, const float4& xq1,
                                         const float4& xq2, const float4& xq3,
                                         float* __restrict__ outb,
                                         int i0, int t) {
    constexpr int D = Dof(R);
    static_assert(D + 3 <= 20);
    const int v = N - i0 - D;            // 4*n_r; <= 0 for rows fully scalar
    if (lane_ok && v > 0 && t < (v >> 2)) {
        const int i = i0 + R;
        const float xi = pick<R>(xq0, xq1, xq2, xq3);       // x[i0+R]
        const int base = i * N - triang(i + 1);
        float4 o;
        o.x = pick6<D    >(w0, w1, w2, w3, w4, w20) * xi;
        o.y = pick6<D + 1>(w0, w1, w2, w3, w4, w20) * xi;
        o.z = pick6<D + 2>(w0, w1, w2, w3, w4, w20) * xi;
        o.w = pick6<D + 3>(w0, w1, w2, w3, w4, w20) * xi;
        // (base + i0 + D) % 4 == 0 by construction -> aligned STG.128
        __stcs(reinterpret_cast<float4*>(outb + base + i0 + D) + t, o);
    }
}

// One 16-row tile: 5 clamped LDG.128 + 1 clamped scalar load, then 16
// predicated row stores (xq loaded lazily, L1-hit). Caller guarantees at
// least one lane in the warp is active.
__device__ __forceinline__ void do_tile16(const float4* __restrict__ xr4,
                                          const float* __restrict__ xrow,
                                          float* __restrict__ outb,
                                          int i0, int t, bool ok) {
    // Clamp t (inactive lanes) and overfetch words; clamped slots are only
    // consumed by lanes/rows whose predicate is false (if t < n_r, every
    // needed x index i0+4t+k <= N-1 -> containing word <= M4LAST and the
    // scalar index <= N-1).
    const int tc = t > M4LAST ? M4LAST : t;
    const int m  = (i0 >> 2) + tc;
    const int mc = m > M4LAST ? M4LAST : m;
    const float4 w0 = __ldg(xr4 + mc);
    const float4 w1 = __ldg(xr4 + (mc + 1 > M4LAST ? M4LAST : mc + 1));
    const float4 w2 = __ldg(xr4 + (mc + 2 > M4LAST ? M4LAST : mc + 2));
    const float4 w3 = __ldg(xr4 + (mc + 3 > M4LAST ? M4LAST : mc + 3));
    const float4 w4 = __ldg(xr4 + (mc + 4 > M4LAST ? M4LAST : mc + 4));
    const int s = 4 * mc + 20;
    const float w20 = __ldg(xrow + (s > N - 1 ? N - 1 : s));

    const float4 xq0 = __ldg(xr4 + (i0 >> 2));        // x[i0   .. i0+3 ]
    const float4 xq1 = __ldg(xr4 + (i0 >> 2) + 1);    // x[i0+4 .. i0+7 ]
    const float4 xq2 = __ldg(xr4 + (i0 >> 2) + 2);    // x[i0+8 .. i0+11]
    const float4 xq3 = __ldg(xr4 + (i0 >> 2) + 3);    // x[i0+12.. i0+15]
    tile_row<0 >(ok, w0, w1, w2, w3, w4, w20, xq0, xq1, xq2, xq3, outb, i0, t);
    tile_row<1 >(ok, w0, w1, w2, w3, w4, w20, xq0, xq1, xq2, xq3, outb, i0, t);
    tile_row<2 >(ok, w0, w1, w2, w3, w4, w20, xq0, xq1, xq2, xq3, outb, i0, t);
    tile_row<3 >(ok, w0, w1, w2, w3, w4, w20, xq0, xq1, xq2, xq3, outb, i0, t);
    tile_row<4 >(ok, w0, w1, w2, w3, w4, w20, xq0, xq1, xq2, xq3, outb, i0, t);
    tile_row<5 >(ok, w0, w1, w2, w3, w4, w20, xq0, xq1, xq2, xq3, outb, i0, t);
    tile_row<6 >(ok, w0, w1, w2, w3, w4, w20, xq0, xq1, xq2, xq3, outb, i0, t);
    tile_row<7 >(ok, w0, w1, w2, w3, w4, w20, xq0, xq1, xq2, xq3, outb, i0, t);
    tile_row<8 >(ok, w0, w1, w2, w3, w4, w20, xq0, xq1, xq2, xq3, outb, i0, t);
    tile_row<9 >(ok, w0, w1, w2, w3, w4, w20, xq0, xq1, xq2, xq3, outb, i0, t);
    tile_row<10>(ok, w0, w1, w2, w3, w4, w20, xq0, xq1, xq2, xq3, outb, i0, t);
    tile_row<11>(ok, w0, w1, w2, w3, w4, w20, xq0, xq1, xq2, xq3, outb, i0, t);
    tile_row<12>(ok, w0, w1, w2, w3, w4, w20, xq0, xq1, xq2, xq3, outb, i0, t);
    tile_row<13>(ok, w0, w1, w2, w3, w4, w20, xq0, xq1, xq2, xq3, outb, i0, t);
    tile_row<14>(ok, w0, w1, w2, w3, w4, w20, xq0, xq1, xq2, xq3, outb, i0, t);
    tile_row<15>(ok, w0, w1, w2, w3, w4, w20, xq0, xq1, xq2, xq3, outb, i0, t);
}

__global__ __launch_bounds__(THREADS, 6)
void selmul_kernel(const float* __restrict__ x, float* __restrict__ out) {
    const int q   = blockIdx.x;        // 0..31
    const int i0A = 16 * q;            // 0..496
    const int i0B = 1008 - 16 * q;     // 1008..512  (both % 16 == 0)
    const int t   = threadIdx.x;
    const int tr  = THREADS - 1 - t;   // reversed lanes: low warps serve tile A,
                                       // high warps serve tile B (nmaxA+nmaxB=260).
    const int b   = blockIdx.y;        // one batch row per CTA (BB=1)

    const float*  xrow = x + b * N;
    const float4* xr4  = reinterpret_cast<const float4*>(xrow);
    float* outb = out + b * TRI;       // max elem offset < 2^27: int-safe

    // Scalar heads + tails for the 32 rows of both tiles (<= 6 elems each;
    // rows with fj >= N are covered entirely here).
    if (t < 32) {
        const int i0 = (t & 16) ? i0B : i0A;
        const int i  = i0 + (t & 15);
        const int Tn = triang(i + 1);
        const int base = i * N - Tn;
        const int fj = i + ((((Tn & 3) - (i & 3)) + 4) & 3); // first aligned j
        const float xi = __ldg(xrow + i);
        const int he = fj < N ? fj : N;
        for (int j = i; j < he; ++j)
            __stcs(outb + base + j, xi * __ldg(xrow + j));
        const int nv = (N > fj) ? ((N - fj) >> 2) : 0;
        for (int j = fj + 4 * nv; j < N; ++j)
            __stcs(outb + base + j, xi * __ldg(xrow + j));
    }

    const bool okA = t  < ((N - i0A) >> 2);
    const bool okB = tr < ((N - i0B) >> 2);

    // Warp-uniform skip: predicates warp-contiguous (lane reversal), so most
    // warps execute exactly one tile (loads AND stores of the other skipped).
    const bool anyA = __any_sync(0xffffffffu, okA);
    const bool anyB = __any_sync(0xffffffffu, okB);
    if (anyA) do_tile16(xr4, xrow, outb, i0A, t,  okA);
    if (anyB) do_tile16(xr4, xrow, outb, i0B, tr, okB);
}

extern "C" void kernel_launch(void* const* d_in, const int* in_sizes, int n_in,
                              void* d_out, int out_size) {
    (void)in_sizes; (void)n_in; (void)out_size;
    const float* x = (const float*)d_in[0];
    float* out = (float*)d_out;

    dim3 grid(N / 32, B);   // 32 tile-pairs x 256 batches = 8192 blocks
    dim3 block(THREADS);
    selmul_kernel<<<grid, block>>>(x, out);
}

// round 17
// speedup vs baseline: 1.5610x; 1.5610x over previous
#include <cuda_runtime.h>

// SelMul: pair (i,j), i<=j, row-major triangular:
//   offset(i,j) = i*N - T(i+1) + j,  T(k) = k(k-1)/2,  value x[b,i]*x[b,j].
// x: (256,1024) fp32 -> out: (256,524800) fp32 (~537 MB). Store-bound.
//
// R16 = R15 with the register cap REMOVED (launch_bounds(256), no min-CTA).
// R15's launch_bounds(256,6) forced the 16-row tile's ~44-float live set into
// local-memory spills (regs=40, L1 82.8%, DRAM 44.4%, 137us). R12 proved the
// same tile at regs=64 runs spill-free with the LOWEST L1 of any variant
// (62.2%); R13 proved occupancy 40% vs 53% is performance-neutral here. So:
// free registers + R14's geometry fixes (8192 CTAs, warp-uniform skip).
// Indexing identical to R12/R15 (proven): tile rows i0..i0+15, i0 % 16 == 0;
//   D(r) = r + ((T(r+1)&3 - r) & 3) = {0,1,3,6,6,7,9,8,8,9,11,14,14,15,17,16},
//   max D+3 = 20 -> w[0..19] from 5 LDG.128 plus scalar w20 (pick6 statically
//   bounds-checked). Heads/tails scalar via the same congruence.

static constexpr int N       = 1024;
static constexpr int B       = 256;
static constexpr int TRI     = N * (N + 1) / 2;   // 524800
static constexpr int THREADS = 256;
static constexpr int M4LAST  = N / 4 - 1;         // 255

__host__ __device__ constexpr int triang(int k) { return k * (k - 1) / 2; }
__host__ __device__ constexpr int Dof(int r) {
    return r + ((((triang(r + 1) & 3) - r) + 16) & 3);
}

// Select float K (0..15) from four float4s.
template <int K>
__device__ __forceinline__ float pick(const float4& a, const float4& b,
                                      const float4& c, const float4& d) {
    static_assert(K >= 0 && K <= 15);
    if constexpr (K == 0)  return a.x;
    else if constexpr (K == 1)  return a.y;
    else if constexpr (K == 2)  return a.z;
    else if constexpr (K == 3)  return a.w;
    else if constexpr (K == 4)  return b.x;
    else if constexpr (K == 5)  return b.y;
    else if constexpr (K == 6)  return b.z;
    else if constexpr (K == 7)  return b.w;
    else if constexpr (K == 8)  return c.x;
    else if constexpr (K == 9)  return c.y;
    else if constexpr (K == 10) return c.z;
    else if constexpr (K == 11) return c.w;
    else if constexpr (K == 12) return d.x;
    else if constexpr (K == 13) return d.y;
    else if constexpr (K == 14) return d.z;
    else return d.w;
}

// Select float K (0..20) from five float4s + one scalar (w[20]).
template <int K>
__device__ __forceinline__ float pick6(const float4& a, const float4& b,
                                       const float4& c, const float4& d,
                                       const float4& e, float w20) {
    static_assert(K >= 0 && K <= 20);
    if constexpr (K < 16)       return pick<K>(a, b, c, d);
    else if constexpr (K == 16) return e.x;
    else if constexpr (K == 17) return e.y;
    else if constexpr (K == 18) return e.z;
    else if constexpr (K == 19) return e.w;
    else                        return w20;
}

template <int R>
__device__ __forceinline__ void tile_row(bool lane_ok,
                                         const float4& w0, const float4& w1,
                                         const float4& w2, const float4& w3,
                                         const float4& w4, float w20,
                                         const float4& xq0, const float4& xq1,
                                         const float4& xq2, const float4& xq3,
                                         float* __restrict__ outb,
                                         int i0, int t) {
    constexpr int D = Dof(R);
    static_assert(D + 3 <= 20);
    const int v = N - i0 - D;            // 4*n_r; <= 0 for rows fully scalar
    if (lane_ok && v > 0 && t < (v >> 2)) {
        const int i = i0 + R;
        const float xi = pick<R>(xq0, xq1, xq2, xq3);       // x[i0+R]
        const int base = i * N - triang(i + 1);
        float4 o;
        o.x = pick6<D    >(w0, w1, w2, w3, w4, w20) * xi;
        o.y = pick6<D + 1>(w0, w1, w2, w3, w4, w20) * xi;
        o.z = pick6<D + 2>(w0, w1, w2, w3, w4, w20) * xi;
        o.w = pick6<D + 3>(w0, w1, w2, w3, w4, w20) * xi;
        // (base + i0 + D) % 4 == 0 by construction -> aligned STG.128
        __stcs(reinterpret_cast<float4*>(outb + base + i0 + D) + t, o);
    }
}

// One 16-row tile: 5 clamped LDG.128 + 1 clamped scalar load, then 16
// predicated row stores (xq loaded lazily, L1-hit). Caller guarantees at
// least one lane in the warp is active.
__device__ __forceinline__ void do_tile16(const float4* __restrict__ xr4,
                                          const float* __restrict__ xrow,
                                          float* __restrict__ outb,
                                          int i0, int t, bool ok) {
    // Clamp t (inactive lanes) and overfetch words; clamped slots are only
    // consumed by lanes/rows whose predicate is false (if t < n_r, every
    // needed x index i0+4t+k <= N-1 -> containing word <= M4LAST and the
    // scalar index <= N-1).
    const int tc = t > M4LAST ? M4LAST : t;
    const int m  = (i0 >> 2) + tc;
    const int mc = m > M4LAST ? M4LAST : m;
    const float4 w0 = __ldg(xr4 + mc);
    const float4 w1 = __ldg(xr4 + (mc + 1 > M4LAST ? M4LAST : mc + 1));
    const float4 w2 = __ldg(xr4 + (mc + 2 > M4LAST ? M4LAST : mc + 2));
    const float4 w3 = __ldg(xr4 + (mc + 3 > M4LAST ? M4LAST : mc + 3));
    const float4 w4 = __ldg(xr4 + (mc + 4 > M4LAST ? M4LAST : mc + 4));
    const int s = 4 * mc + 20;
    const float w20 = __ldg(xrow + (s > N - 1 ? N - 1 : s));

    const float4 xq0 = __ldg(xr4 + (i0 >> 2));        // x[i0   .. i0+3 ]
    const float4 xq1 = __ldg(xr4 + (i0 >> 2) + 1);    // x[i0+4 .. i0+7 ]
    const float4 xq2 = __ldg(xr4 + (i0 >> 2) + 2);    // x[i0+8 .. i0+11]
    const float4 xq3 = __ldg(xr4 + (i0 >> 2) + 3);    // x[i0+12.. i0+15]
    tile_row<0 >(ok, w0, w1, w2, w3, w4, w20, xq0, xq1, xq2, xq3, outb, i0, t);
    tile_row<1 >(ok, w0, w1, w2, w3, w4, w20, xq0, xq1, xq2, xq3, outb, i0, t);
    tile_row<2 >(ok, w0, w1, w2, w3, w4, w20, xq0, xq1, xq2, xq3, outb, i0, t);
    tile_row<3 >(ok, w0, w1, w2, w3, w4, w20, xq0, xq1, xq2, xq3, outb, i0, t);
    tile_row<4 >(ok, w0, w1, w2, w3, w4, w20, xq0, xq1, xq2, xq3, outb, i0, t);
    tile_row<5 >(ok, w0, w1, w2, w3, w4, w20, xq0, xq1, xq2, xq3, outb, i0, t);
    tile_row<6 >(ok, w0, w1, w2, w3, w4, w20, xq0, xq1, xq2, xq3, outb, i0, t);
    tile_row<7 >(ok, w0, w1, w2, w3, w4, w20, xq0, xq1, xq2, xq3, outb, i0, t);
    tile_row<8 >(ok, w0, w1, w2, w3, w4, w20, xq0, xq1, xq2, xq3, outb, i0, t);
    tile_row<9 >(ok, w0, w1, w2, w3, w4, w20, xq0, xq1, xq2, xq3, outb, i0, t);
    tile_row<10>(ok, w0, w1, w2, w3, w4, w20, xq0, xq1, xq2, xq3, outb, i0, t);
    tile_row<11>(ok, w0, w1, w2, w3, w4, w20, xq0, xq1, xq2, xq3, outb, i0, t);
    tile_row<12>(ok, w0, w1, w2, w3, w4, w20, xq0, xq1, xq2, xq3, outb, i0, t);
    tile_row<13>(ok, w0, w1, w2, w3, w4, w20, xq0, xq1, xq2, xq3, outb, i0, t);
    tile_row<14>(ok, w0, w1, w2, w3, w4, w20, xq0, xq1, xq2, xq3, outb, i0, t);
    tile_row<15>(ok, w0, w1, w2, w3, w4, w20, xq0, xq1, xq2, xq3, outb, i0, t);
}

__global__ __launch_bounds__(THREADS)   // NO min-CTA cap: let ptxas use ~64 regs
void selmul_kernel(const float* __restrict__ x, float* __restrict__ out) {
    const int q   = blockIdx.x;        // 0..31
    const int i0A = 16 * q;            // 0..496
    const int i0B = 1008 - 16 * q;     // 1008..512  (both % 16 == 0)
    const int t   = threadIdx.x;
    const int tr  = THREADS - 1 - t;   // reversed lanes: low warps serve tile A,
                                       // high warps serve tile B (nmaxA+nmaxB=260).
    const int b   = blockIdx.y;        // one batch row per CTA

    const float*  xrow = x + b * N;
    const float4* xr4  = reinterpret_cast<const float4*>(xrow);
    float* outb = out + b * TRI;       // max elem offset < 2^27: int-safe

    // Scalar heads + tails for the 32 rows of both tiles (<= 6 elems each;
    // rows with fj >= N are covered entirely here).
    if (t < 32) {
        const int i0 = (t & 16) ? i0B : i0A;
        const int i  = i0 + (t & 15);
        const int Tn = triang(i + 1);
        const int base = i * N - Tn;
        const int fj = i + ((((Tn & 3) - (i & 3)) + 4) & 3); // first aligned j
        const float xi = __ldg(xrow + i);
        const int he = fj < N ? fj : N;
        for (int j = i; j < he; ++j)
            __stcs(outb + base + j, xi * __ldg(xrow + j));
        const int nv = (N > fj) ? ((N - fj) >> 2) : 0;
        for (int j = fj + 4 * nv; j < N; ++j)
            __stcs(outb + base + j, xi * __ldg(xrow + j));
    }

    const bool okA = t  < ((N - i0A) >> 2);
    const bool okB = tr < ((N - i0B) >> 2);

    // Warp-uniform skip: predicates warp-contiguous (lane reversal), so most
    // warps execute exactly one tile (loads AND stores of the other skipped).
    const bool anyA = __any_sync(0xffffffffu, okA);
    const bool anyB = __any_sync(0xffffffffu, okB);
    if (anyA) do_tile16(xr4, xrow, outb, i0A, t,  okA);
    if (anyB) do_tile16(xr4, xrow, outb, i0B, tr, okB);
}

extern "C" void kernel_launch(void* const* d_in, const int* in_sizes, int n_in,
                              void* d_out, int out_size) {
    (void)in_sizes; (void)n_in; (void)out_size;
    const float* x = (const float*)d_in[0];
    float* out = (float*)d_out;

    dim3 grid(N / 32, B);   // 32 tile-pairs x 256 batches = 8192 blocks
    dim3 block(THREADS);
    selmul_kernel<<<grid, block>>>(x, out);
}